// round 1
// baseline (speedup 1.0000x reference)
#include <cuda_runtime.h>
#include <math.h>

#define BB 1024
#define TT 100
#define HH 256
#define H2 512
#define G4 1024

// ---------------- device scratch (allocated at module load; allowed) ----------
__device__ float d_m[BB];
__device__ float d_h1[2][2][BB*HH];   // [ping][dir][b*H+h]
__device__ float d_c1[2][BB*HH];      // [dir]
__device__ float d_h2[2][2][BB*HH];
__device__ float d_c2[2][BB*HH];
__device__ float d_p1[TT][BB][H2];    // layer1 outputs (fwd | bwd halves)
__device__ float d_p2[TT][BB][H2];    // layer2 outputs

// ---------------- helpers ------------------------------------------------------
__device__ __forceinline__ float sigf(float x) { return 1.0f / (1.0f + __expf(-x)); }

// ---------------- mean over time -----------------------------------------------
__global__ void mean_kernel(const float* __restrict__ x0) {
    int b = blockIdx.x * blockDim.x + threadIdx.x;
    if (b < BB) {
        float s = 0.f;
        #pragma unroll 4
        for (int t = 0; t < TT; t++) s += x0[b * TT + t];
        d_m[b] = s * (1.0f / TT);
    }
}

// ---------------- zero initial states ------------------------------------------
__global__ void zero_kernel() {
    int i = blockIdx.x * blockDim.x + threadIdx.x;
    if (i < BB * HH) {
        d_h1[0][0][i] = 0.f; d_h1[0][1][i] = 0.f;
        d_c1[0][i] = 0.f;    d_c1[1][i] = 0.f;
        d_h2[0][0][i] = 0.f; d_h2[0][1][i] = 0.f;
        d_c2[0][i] = 0.f;    d_c2[1][i] = 0.f;
    }
}

// ---------------- layer-1 step: gates = (h*mask1)@Whh^T + Wih@x + b ------------
// grid (8 h-tiles, 16 b-tiles, 2 dirs), block 256.
// tile: 64 b x 32 h (=128 gate cols). thread: tx=h, ty=b-group; 8b x 4gates accs.
__global__ void __launch_bounds__(256, 2) lstm1_step(
    int t, int ping,
    const float* __restrict__ x0,
    const float* __restrict__ Wih_f, const float* __restrict__ Whh_f,
    const float* __restrict__ bih_f, const float* __restrict__ bhh_f,
    const float* __restrict__ Wih_b, const float* __restrict__ Whh_b,
    const float* __restrict__ bih_b, const float* __restrict__ bhh_b,
    const float* __restrict__ mask1)
{
    int dir = blockIdx.z;
    const float* Wih = dir ? Wih_b : Wih_f;
    const float* Whh = dir ? Whh_b : Whh_f;
    const float* bih = dir ? bih_b : bih_f;
    const float* bhh = dir ? bhh_b : bhh_f;
    int tin = dir ? (TT - 1 - t) : t;

    const float* h_in  = d_h1[ping][dir];
    float*       h_out = d_h1[ping ^ 1][dir];
    float*       cst   = d_c1[dir];

    int hbase = blockIdx.x * 32;
    int bbase = blockIdx.y * 64;
    int tid = threadIdx.x;
    int tx = tid & 31;    // h within tile
    int ty = tid >> 5;    // 0..7

    __shared__ float sH[64][33];
    __shared__ float sW[128][33];

    float acc[8][4];
    #pragma unroll
    for (int i = 0; i < 8; i++)
        #pragma unroll
        for (int g = 0; g < 4; g++) acc[i][g] = 0.f;

    for (int k0 = 0; k0 < HH; k0 += 32) {
        #pragma unroll
        for (int j = 0; j < 8; j++) {
            int lin = tid + j * 256;
            int bl = lin >> 5, k = lin & 31;
            int gi = (bbase + bl) * HH + k0 + k;
            sH[bl][k] = h_in[gi] * mask1[gi];
        }
        #pragma unroll
        for (int j = 0; j < 16; j++) {
            int lin = tid + j * 256;
            int rl = lin >> 5, k = lin & 31;
            int row = (rl >> 5) * HH + hbase + (rl & 31);
            sW[rl][k] = Whh[row * HH + k0 + k];
        }
        __syncthreads();
        #pragma unroll
        for (int k = 0; k < 32; k++) {
            float wv[4];
            #pragma unroll
            for (int g = 0; g < 4; g++) wv[g] = sW[g * 32 + tx][k];
            #pragma unroll
            for (int i = 0; i < 8; i++) {
                float hv = sH[i * 8 + ty][k];
                #pragma unroll
                for (int g = 0; g < 4; g++) acc[i][g] += hv * wv[g];
            }
        }
        __syncthreads();
    }

    int h = hbase + tx;
    float wi0[4], wi1[4], bbv[4];
    #pragma unroll
    for (int g = 0; g < 4; g++) {
        int r = g * HH + h;
        wi0[g] = Wih[r * 2 + 0];
        wi1[g] = Wih[r * 2 + 1];
        bbv[g] = bih[r] + bhh[r];
    }
    #pragma unroll
    for (int i = 0; i < 8; i++) {
        int b = bbase + i * 8 + ty;
        float mb = d_m[b];
        float xv = x0[b * TT + tin] - mb;
        int sidx = b * HH + h;
        float gi = acc[i][0] + wi0[0] * xv + wi1[0] * mb + bbv[0];
        float gf = acc[i][1] + wi0[1] * xv + wi1[1] * mb + bbv[1];
        float gg = acc[i][2] + wi0[2] * xv + wi1[2] * mb + bbv[2];
        float go = acc[i][3] + wi0[3] * xv + wi1[3] * mb + bbv[3];
        float ig = sigf(gi), fg = sigf(gf), og = sigf(go);
        float gt = tanhf(gg);
        float cn = fg * cst[sidx] + ig * gt;
        float hn = og * tanhf(cn);
        cst[sidx] = cn;
        h_out[sidx] = hn;
        d_p1[t][b][dir * HH + h] = hn;
    }
}

// ---------------- layer-2 step: gates = (p1*mask2)@Wih^T + (h*mask3)@Whh^T + b --
__global__ void __launch_bounds__(256, 2) lstm2_step(
    int t, int ping,
    const float* __restrict__ Wih_f, const float* __restrict__ Whh_f,
    const float* __restrict__ bih_f, const float* __restrict__ bhh_f,
    const float* __restrict__ Wih_b, const float* __restrict__ Whh_b,
    const float* __restrict__ bih_b, const float* __restrict__ bhh_b,
    const float* __restrict__ mask2, const float* __restrict__ mask3)
{
    int dir = blockIdx.z;
    const float* Wih = dir ? Wih_b : Wih_f;
    const float* Whh = dir ? Whh_b : Whh_f;
    const float* bih = dir ? bih_b : bih_f;
    const float* bhh = dir ? bhh_b : bhh_f;
    int tin = dir ? (TT - 1 - t) : t;

    const float* h_in  = d_h2[ping][dir];
    float*       h_out = d_h2[ping ^ 1][dir];
    float*       cst   = d_c2[dir];

    int hbase = blockIdx.x * 32;
    int bbase = blockIdx.y * 64;
    int tid = threadIdx.x;
    int tx = tid & 31;
    int ty = tid >> 5;

    __shared__ float sH[64][33];
    __shared__ float sW[128][33];

    float acc[8][4];
    #pragma unroll
    for (int i = 0; i < 8; i++)
        #pragma unroll
        for (int g = 0; g < 4; g++) acc[i][g] = 0.f;

    // segment 1: input contribution, K = 512 over p1[tin]*mask2
    for (int k0 = 0; k0 < H2; k0 += 32) {
        #pragma unroll
        for (int j = 0; j < 8; j++) {
            int lin = tid + j * 256;
            int bl = lin >> 5, k = lin & 31;
            int b = bbase + bl;
            sH[bl][k] = d_p1[tin][b][k0 + k] * mask2[b * H2 + k0 + k];
        }
        #pragma unroll
        for (int j = 0; j < 16; j++) {
            int lin = tid + j * 256;
            int rl = lin >> 5, k = lin & 31;
            int row = (rl >> 5) * HH + hbase + (rl & 31);
            sW[rl][k] = Wih[row * H2 + k0 + k];
        }
        __syncthreads();
        #pragma unroll
        for (int k = 0; k < 32; k++) {
            float wv[4];
            #pragma unroll
            for (int g = 0; g < 4; g++) wv[g] = sW[g * 32 + tx][k];
            #pragma unroll
            for (int i = 0; i < 8; i++) {
                float hv = sH[i * 8 + ty][k];
                #pragma unroll
                for (int g = 0; g < 4; g++) acc[i][g] += hv * wv[g];
            }
        }
        __syncthreads();
    }

    // segment 2: recurrent contribution, K = 256 over h*mask3
    for (int k0 = 0; k0 < HH; k0 += 32) {
        #pragma unroll
        for (int j = 0; j < 8; j++) {
            int lin = tid + j * 256;
            int bl = lin >> 5, k = lin & 31;
            int gi = (bbase + bl) * HH + k0 + k;
            sH[bl][k] = h_in[gi] * mask3[gi];
        }
        #pragma unroll
        for (int j = 0; j < 16; j++) {
            int lin = tid + j * 256;
            int rl = lin >> 5, k = lin & 31;
            int row = (rl >> 5) * HH + hbase + (rl & 31);
            sW[rl][k] = Whh[row * HH + k0 + k];
        }
        __syncthreads();
        #pragma unroll
        for (int k = 0; k < 32; k++) {
            float wv[4];
            #pragma unroll
            for (int g = 0; g < 4; g++) wv[g] = sW[g * 32 + tx][k];
            #pragma unroll
            for (int i = 0; i < 8; i++) {
                float hv = sH[i * 8 + ty][k];
                #pragma unroll
                for (int g = 0; g < 4; g++) acc[i][g] += hv * wv[g];
            }
        }
        __syncthreads();
    }

    int h = hbase + tx;
    float bbv[4];
    #pragma unroll
    for (int g = 0; g < 4; g++) {
        int r = g * HH + h;
        bbv[g] = bih[r] + bhh[r];
    }
    #pragma unroll
    for (int i = 0; i < 8; i++) {
        int b = bbase + i * 8 + ty;
        int sidx = b * HH + h;
        float gi = acc[i][0] + bbv[0];
        float gf = acc[i][1] + bbv[1];
        float gg = acc[i][2] + bbv[2];
        float go = acc[i][3] + bbv[3];
        float ig = sigf(gi), fg = sigf(gf), og = sigf(go);
        float gt = tanhf(gg);
        float cn = fg * cst[sidx] + ig * gt;
        float hn = og * tanhf(cn);
        cst[sidx] = cn;
        h_out[sidx] = hn;
        d_p2[t][b][dir * HH + h] = hn;
    }
}

// ---------------- output projection: out[b,t] = p2[t][b] . (mask4*Wout) + bout + m
__global__ void proj_kernel(const float* __restrict__ Wout,
                            const float* __restrict__ bout,
                            const float* __restrict__ mask4,
                            float* __restrict__ out)
{
    int w = blockIdx.x * (blockDim.x >> 5) + (threadIdx.x >> 5);
    int lane = threadIdx.x & 31;
    if (w >= BB * TT) return;
    int b = w / TT, t = w % TT;
    float s = 0.f;
    #pragma unroll
    for (int j = lane; j < H2; j += 32)
        s += d_p2[t][b][j] * mask4[b * H2 + j] * Wout[j];
    #pragma unroll
    for (int o = 16; o > 0; o >>= 1) s += __shfl_xor_sync(0xffffffffu, s, o);
    if (lane == 0) out[b * TT + t] = s + bout[0] + d_m[b];
}

// ---------------- launcher -----------------------------------------------------
extern "C" void kernel_launch(void* const* d_in, const int* in_sizes, int n_in,
                              void* d_out, int out_size)
{
    const float* x0    = (const float*)d_in[0];
    const float* Wih1f = (const float*)d_in[1];
    const float* Whh1f = (const float*)d_in[2];
    const float* bih1f = (const float*)d_in[3];
    const float* bhh1f = (const float*)d_in[4];
    const float* Wih1b = (const float*)d_in[5];
    const float* Whh1b = (const float*)d_in[6];
    const float* bih1b = (const float*)d_in[7];
    const float* bhh1b = (const float*)d_in[8];
    const float* Wih2f = (const float*)d_in[9];
    const float* Whh2f = (const float*)d_in[10];
    const float* bih2f = (const float*)d_in[11];
    const float* bhh2f = (const float*)d_in[12];
    const float* Wih2b = (const float*)d_in[13];
    const float* Whh2b = (const float*)d_in[14];
    const float* bih2b = (const float*)d_in[15];
    const float* bhh2b = (const float*)d_in[16];
    const float* Wout  = (const float*)d_in[17];
    const float* bout  = (const float*)d_in[18];
    const float* mask1 = (const float*)d_in[19];
    const float* mask2 = (const float*)d_in[20];
    const float* mask3 = (const float*)d_in[21];
    const float* mask4 = (const float*)d_in[22];
    float* out = (float*)d_out;

    mean_kernel<<<(BB + 255) / 256, 256>>>(x0);
    zero_kernel<<<(BB * HH + 255) / 256, 256>>>();

    dim3 sgrid(HH / 32, BB / 64, 2);   // (8, 16, 2)
    int ping = 0;
    for (int t = 0; t < TT; t++) {
        lstm1_step<<<sgrid, 256>>>(t, ping, x0,
                                   Wih1f, Whh1f, bih1f, bhh1f,
                                   Wih1b, Whh1b, bih1b, bhh1b, mask1);
        ping ^= 1;
    }
    ping = 0;
    for (int t = 0; t < TT; t++) {
        lstm2_step<<<sgrid, 256>>>(t, ping,
                                   Wih2f, Whh2f, bih2f, bhh2f,
                                   Wih2b, Whh2b, bih2b, bhh2b, mask2, mask3);
        ping ^= 1;
    }
    proj_kernel<<<(BB * TT + 7) / 8, 256>>>(Wout, bout, mask4, out);
}

// round 3
// speedup vs baseline: 1.4801x; 1.4801x over previous
#include <cuda_runtime.h>
#include <cuda_bf16.h>
#include <mma.h>
#include <cstdint>
#include <math.h>

using namespace nvcuda;

#define BB 1024
#define TT 100
#define HH 256
#define H2 512

// ---------------- device scratch ----------------
__device__ float d_m[BB];
__device__ float d_h1[2][2][BB*HH];
__device__ float d_c1[2][BB*HH];
__device__ float d_h2[2][2][BB*HH];
__device__ float d_c2[2][BB*HH];
__device__ float d_p1[TT][BB][H2];
__device__ float d_p2[TT][BB][H2];

__device__ __nv_bfloat16 d_W1hi[2][1024*256];
__device__ __nv_bfloat16 d_W1lo[2][1024*256];
__device__ __nv_bfloat16 d_W2hi[2][1024*768];
__device__ __nv_bfloat16 d_W2lo[2][1024*768];
__device__ float d_bx1[2][1024];
__device__ float d_bx2[2][1024];
__device__ float d_wix[2][1024*2];

__device__ __forceinline__ float sigf(float x){ return 1.0f/(1.0f+__expf(-x)); }

// ---------------- mean ----------------
__global__ void mean_kernel(const float* __restrict__ x0){
    int b = blockIdx.x*blockDim.x + threadIdx.x;
    if (b < BB){
        float s = 0.f;
        #pragma unroll 4
        for (int t=0; t<TT; t++) s += x0[b*TT+t];
        d_m[b] = s*(1.0f/TT);
    }
}

// ---------------- zero states ----------------
__global__ void zero_kernel(){
    int i = blockIdx.x*blockDim.x + threadIdx.x;
    if (i < BB*HH){
        d_h1[0][0][i]=0.f; d_h1[0][1][i]=0.f; d_c1[0][i]=0.f; d_c1[1][i]=0.f;
        d_h2[0][0][i]=0.f; d_h2[0][1][i]=0.f; d_c2[0][i]=0.f; d_c2[1][i]=0.f;
    }
}

// ---------------- weight prep: split + permute (r' = 4h+g) ----------------
__global__ void prep_weights(
    const float* __restrict__ Whh1f, const float* __restrict__ Whh1b,
    const float* __restrict__ Wih2f, const float* __restrict__ Whh2f,
    const float* __restrict__ Wih2b, const float* __restrict__ Whh2b,
    const float* __restrict__ Wih1f, const float* __restrict__ Wih1b,
    const float* __restrict__ bih1f, const float* __restrict__ bhh1f,
    const float* __restrict__ bih1b, const float* __restrict__ bhh1b,
    const float* __restrict__ bih2f, const float* __restrict__ bhh2f,
    const float* __restrict__ bih2b, const float* __restrict__ bhh2b)
{
    int stride = gridDim.x*blockDim.x;
    int idx = blockIdx.x*blockDim.x + threadIdx.x;
    for (int i = idx; i < 2*1024*256; i += stride){
        int dir = i/(1024*256); int r = (i/256)%1024; int k = i%256;
        int h = r>>2, g = r&3;
        const float* W = dir ? Whh1b : Whh1f;
        float w = W[(g*256+h)*256 + k];
        __nv_bfloat16 hi = __float2bfloat16(w);
        __nv_bfloat16 lo = __float2bfloat16(w - __bfloat162float(hi));
        d_W1hi[dir][r*256+k] = hi;
        d_W1lo[dir][r*256+k] = lo;
    }
    for (int i = idx; i < 2*1024*768; i += stride){
        int dir = i/(1024*768); int r = (i/768)%1024; int k = i%768;
        int h = r>>2, g = r&3;
        float w;
        if (k < 512){
            const float* W = dir ? Wih2b : Wih2f;
            w = W[(g*256+h)*512 + k];
        } else {
            const float* W = dir ? Whh2b : Whh2f;
            w = W[(g*256+h)*256 + (k-512)];
        }
        __nv_bfloat16 hi = __float2bfloat16(w);
        __nv_bfloat16 lo = __float2bfloat16(w - __bfloat162float(hi));
        d_W2hi[dir][r*768+k] = hi;
        d_W2lo[dir][r*768+k] = lo;
    }
    for (int i = idx; i < 2*1024; i += stride){
        int dir = i>>10; int r = i&1023;
        int h = r>>2, g = r&3;
        const float* b1i = dir ? bih1b : bih1f; const float* b1h = dir ? bhh1b : bhh1f;
        const float* b2i = dir ? bih2b : bih2f; const float* b2h = dir ? bhh2b : bhh2f;
        d_bx1[dir][r] = b1i[g*256+h] + b1h[g*256+h];
        d_bx2[dir][r] = b2i[g*256+h] + b2h[g*256+h];
        const float* Wi = dir ? Wih1b : Wih1f;
        d_wix[dir][r*2+0] = Wi[(g*256+h)*2 + 0];
        d_wix[dir][r*2+1] = Wi[(g*256+h)*2 + 1];
    }
}

// ---------------- WMMA LSTM step ----------------
// grid (8 ntiles, 8 btiles, 2 dirs), 256 threads (8 warps).
// CTA tile: M=128 batch x N=128 gate cols; K chunks of 64.
// warp tile 32(M) x 64(N): 2x4 fragments of 16x16.
// 3-pass compensated bf16: c += Ah*Wh + Al*Wh + Ah*Wl.

#define KC 64
#define LDA 72          // smem lead dim (bf16 elems) for A and W chunks
#define LDC 132         // smem lead dim (f32) for C

#define OFF_BIAS 0
#define OFF_WIX  512
#define OFF_UNION 2048
#define ABUF_SZ (128*LDA*2)           // 18432 bytes per buffer
#define SMEM_BYTES (OFF_UNION + 4*ABUF_SZ)   // 75776

template<int LAYER>
__global__ void __launch_bounds__(256, 2) lstm_wmma(
    int t, int ping,
    const float* __restrict__ x0,
    const float* __restrict__ mA,   // layer1: mask1 ; layer2: mask2
    const float* __restrict__ mB)   // layer2: mask3
{
    constexpr int K   = (LAYER==1) ? HH : 768;
    constexpr int NKC = K / KC;

    extern __shared__ char sm[];
    float* sBias = (float*)(sm + OFF_BIAS);
    float* sWix  = (float*)(sm + OFF_WIX);
    __nv_bfloat16* sAh = (__nv_bfloat16*)(sm + OFF_UNION);
    __nv_bfloat16* sAl = (__nv_bfloat16*)(sm + OFF_UNION + ABUF_SZ);
    __nv_bfloat16* sWh = (__nv_bfloat16*)(sm + OFF_UNION + 2*ABUF_SZ);
    __nv_bfloat16* sWl = (__nv_bfloat16*)(sm + OFF_UNION + 3*ABUF_SZ);
    float* sC = (float*)(sm + OFF_UNION);

    const int tid  = threadIdx.x;
    const int wid  = tid>>5;
    const int ntile = blockIdx.x, btile = blockIdx.y, dir = blockIdx.z;
    const int tin = dir ? (TT-1-t) : t;
    const int gr0 = ntile*128;

    const float* h_in;
    float* h_out;
    float* cst;
    const __nv_bfloat16* Whi;
    const __nv_bfloat16* Wlo;
    const float* bx;
    if (LAYER==1){
        h_in = d_h1[ping][dir]; h_out = d_h1[ping^1][dir]; cst = d_c1[dir];
        Whi = d_W1hi[dir]; Wlo = d_W1lo[dir]; bx = d_bx1[dir];
    } else {
        h_in = d_h2[ping][dir]; h_out = d_h2[ping^1][dir]; cst = d_c2[dir];
        Whi = d_W2hi[dir]; Wlo = d_W2lo[dir]; bx = d_bx2[dir];
    }

    if (tid < 128) sBias[tid] = bx[gr0 + tid];
    if (LAYER==1)  sWix[tid]  = d_wix[dir][gr0*2 + tid];

    // accumulators
    wmma::fragment<wmma::accumulator,16,16,16,float> acc[2][4];
    #pragma unroll
    for (int i=0;i<2;i++)
        #pragma unroll
        for (int j=0;j<4;j++) wmma::fill_fragment(acc[i][j], 0.0f);

    const int wm = (wid & 3) * 32;     // warp M offset
    const int wn = (wid >> 2) * 64;    // warp N offset

    for (int kc = 0; kc < NKC; kc++){
        // ---- stage W chunk: rows 128 x 64 k (hi & lo), vectorized 16B ----
        #pragma unroll
        for (int it=0; it<4; it++){
            int lin = tid + it*256;          // 1024 uint4 per buffer
            int row = lin>>3, k8 = lin&7;
            const uint4* srcH = (const uint4*)&Whi[(gr0+row)*K + kc*KC + k8*8];
            const uint4* srcL = (const uint4*)&Wlo[(gr0+row)*K + kc*KC + k8*8];
            *(uint4*)((char*)sWh + row*(LDA*2) + k8*16) = *srcH;
            *(uint4*)((char*)sWl + row*(LDA*2) + k8*16) = *srcL;
        }
        // ---- stage A chunk: 128 b x 64 k, fp32 -> bf16 hi/lo split ----
        #pragma unroll
        for (int it=0; it<16; it++){
            int lin = tid + it*256;          // 4096 float2 slots
            int row = lin>>5, pr = lin&31;
            int b = btile*128 + row;
            int kk = kc*KC + pr*2;
            float v0, v1;
            if (LAYER==1){
                float2 hv = *(const float2*)&h_in[b*HH + kk];
                float2 mv = *(const float2*)&mA[b*HH + kk];
                v0 = hv.x*mv.x; v1 = hv.y*mv.y;
            } else {
                if (kk < H2){
                    float2 pv = *(const float2*)&d_p1[tin][b][kk];
                    float2 mv = *(const float2*)&mA[b*H2 + kk];
                    v0 = pv.x*mv.x; v1 = pv.y*mv.y;
                } else {
                    int kr = kk - H2;
                    float2 hv = *(const float2*)&h_in[b*HH + kr];
                    float2 mv = *(const float2*)&mB[b*HH + kr];
                    v0 = hv.x*mv.x; v1 = hv.y*mv.y;
                }
            }
            __nv_bfloat16 h0 = __float2bfloat16(v0);
            __nv_bfloat16 h1 = __float2bfloat16(v1);
            __nv_bfloat16 l0 = __float2bfloat16(v0 - __bfloat162float(h0));
            __nv_bfloat16 l1 = __float2bfloat16(v1 - __bfloat162float(h1));
            uint32_t off = row*(LDA*2) + pr*4;
            *(__nv_bfloat162*)((char*)sAh + off) = __halves2bfloat162(h0, h1);
            *(__nv_bfloat162*)((char*)sAl + off) = __halves2bfloat162(l0, l1);
        }
        __syncthreads();

        // ---- MMA over 4 k16 slices ----
        #pragma unroll
        for (int k16 = 0; k16 < KC/16; k16++){
            wmma::fragment<wmma::matrix_a,16,16,16,__nv_bfloat16,wmma::row_major> ah[2], al[2];
            wmma::fragment<wmma::matrix_b,16,16,16,__nv_bfloat16,wmma::col_major> bh[4], bl[4];
            #pragma unroll
            for (int i=0;i<2;i++){
                wmma::load_matrix_sync(ah[i], sAh + (wm+16*i)*LDA + k16*16, LDA);
                wmma::load_matrix_sync(al[i], sAl + (wm+16*i)*LDA + k16*16, LDA);
            }
            #pragma unroll
            for (int j=0;j<4;j++){
                wmma::load_matrix_sync(bh[j], sWh + (wn+16*j)*LDA + k16*16, LDA);
                wmma::load_matrix_sync(bl[j], sWl + (wn+16*j)*LDA + k16*16, LDA);
            }
            #pragma unroll
            for (int i=0;i<2;i++)
                #pragma unroll
                for (int j=0;j<4;j++){
                    wmma::mma_sync(acc[i][j], ah[i], bh[j], acc[i][j]);
                    wmma::mma_sync(acc[i][j], al[i], bh[j], acc[i][j]);
                    wmma::mma_sync(acc[i][j], ah[i], bl[j], acc[i][j]);
                }
        }
        __syncthreads();
    }

    // ---- dump accumulators to smem C ----
    #pragma unroll
    for (int i=0;i<2;i++)
        #pragma unroll
        for (int j=0;j<4;j++)
            wmma::store_matrix_sync(sC + (wm+16*i)*LDC + wn + 16*j, acc[i][j],
                                    LDC, wmma::mem_row_major);
    __syncthreads();

    // ---- LSTM cell epilogue ----
    {
        int row  = tid >> 1;
        int half = tid & 1;
        int b = btile*128 + row;
        float xv = 0.f, mb = 0.f;
        if (LAYER==1){ mb = d_m[b]; xv = x0[b*TT + tin] - mb; }
        float* pdst = (LAYER==1) ? &d_p1[t][b][0] : &d_p2[t][b][0];
        const float* cr = sC + row*LDC;

        #pragma unroll
        for (int hh=0; hh<16; hh++){
            int rl = half*64 + hh*4;
            float g0 = cr[rl+0] + sBias[rl+0];
            float g1 = cr[rl+1] + sBias[rl+1];
            float g2 = cr[rl+2] + sBias[rl+2];
            float g3 = cr[rl+3] + sBias[rl+3];
            if (LAYER==1){
                g0 += sWix[(rl+0)*2]*xv + sWix[(rl+0)*2+1]*mb;
                g1 += sWix[(rl+1)*2]*xv + sWix[(rl+1)*2+1]*mb;
                g2 += sWix[(rl+2)*2]*xv + sWix[(rl+2)*2+1]*mb;
                g3 += sWix[(rl+3)*2]*xv + sWix[(rl+3)*2+1]*mb;
            }
            int hglob = ntile*32 + half*16 + hh;
            int ci = b*HH + hglob;
            float ig = sigf(g0), fg = sigf(g1), gt = tanhf(g2), og = sigf(g3);
            float cn = fg*cst[ci] + ig*gt;
            float hn = og*tanhf(cn);
            cst[ci] = cn;
            h_out[ci] = hn;
            pdst[dir*HH + hglob] = hn;
        }
    }
}

// ---------------- output projection ----------------
__global__ void proj_kernel(const float* __restrict__ Wout,
                            const float* __restrict__ bout,
                            const float* __restrict__ mask4,
                            float* __restrict__ out)
{
    int w = blockIdx.x*(blockDim.x>>5) + (threadIdx.x>>5);
    int lane = threadIdx.x & 31;
    if (w >= BB*TT) return;
    int b = w/TT, t = w%TT;
    float s = 0.f;
    #pragma unroll
    for (int j = lane; j < H2; j += 32)
        s += d_p2[t][b][j] * mask4[b*H2 + j] * Wout[j];
    #pragma unroll
    for (int o = 16; o > 0; o >>= 1) s += __shfl_xor_sync(0xffffffffu, s, o);
    if (lane == 0) out[b*TT + t] = s + bout[0] + d_m[b];
}

// ---------------- launcher ----------------
extern "C" void kernel_launch(void* const* d_in, const int* in_sizes, int n_in,
                              void* d_out, int out_size)
{
    const float* x0    = (const float*)d_in[0];
    const float* Wih1f = (const float*)d_in[1];
    const float* Whh1f = (const float*)d_in[2];
    const float* bih1f = (const float*)d_in[3];
    const float* bhh1f = (const float*)d_in[4];
    const float* Wih1b = (const float*)d_in[5];
    const float* Whh1b = (const float*)d_in[6];
    const float* bih1b = (const float*)d_in[7];
    const float* bhh1b = (const float*)d_in[8];
    const float* Wih2f = (const float*)d_in[9];
    const float* Whh2f = (const float*)d_in[10];
    const float* bih2f = (const float*)d_in[11];
    const float* bhh2f = (const float*)d_in[12];
    const float* Wih2b = (const float*)d_in[13];
    const float* Whh2b = (const float*)d_in[14];
    const float* bih2b = (const float*)d_in[15];
    const float* bhh2b = (const float*)d_in[16];
    const float* Wout  = (const float*)d_in[17];
    const float* bout  = (const float*)d_in[18];
    const float* mask1 = (const float*)d_in[19];
    const float* mask2 = (const float*)d_in[20];
    const float* mask3 = (const float*)d_in[21];
    const float* mask4 = (const float*)d_in[22];
    float* out = (float*)d_out;

    cudaFuncSetAttribute(lstm_wmma<1>, cudaFuncAttributeMaxDynamicSharedMemorySize, SMEM_BYTES);
    cudaFuncSetAttribute(lstm_wmma<2>, cudaFuncAttributeMaxDynamicSharedMemorySize, SMEM_BYTES);

    mean_kernel<<<(BB+255)/256, 256>>>(x0);
    zero_kernel<<<(BB*HH+255)/256, 256>>>();
    prep_weights<<<1024, 256>>>(Whh1f, Whh1b, Wih2f, Whh2f, Wih2b, Whh2b,
                                Wih1f, Wih1b,
                                bih1f, bhh1f, bih1b, bhh1b,
                                bih2f, bhh2f, bih2b, bhh2b);

    dim3 grid(8, 8, 2);
    int ping = 0;
    for (int t = 0; t < TT; t++){
        lstm_wmma<1><<<grid, 256, SMEM_BYTES>>>(t, ping, x0, mask1, nullptr);
        ping ^= 1;
    }
    ping = 0;
    for (int t = 0; t < TT; t++){
        lstm_wmma<2><<<grid, 256, SMEM_BYTES>>>(t, ping, nullptr, mask2, mask3);
        ping ^= 1;
    }
    proj_kernel<<<(BB*TT+7)/8, 256>>>(Wout, bout, mask4, out);
}

// round 7
// speedup vs baseline: 1.9641x; 1.3270x over previous
#include <cuda_runtime.h>
#include <cuda_bf16.h>
#include <mma.h>
#include <cstdint>
#include <math.h>

using namespace nvcuda;

#define BB 1024
#define TT 100
#define HH 256
#define H2 512
#define LDW 264          // resident W smem lead dim (elems)
#define LDA 72           // A chunk smem lead dim
#define LDC 132          // epilogue C lead dim (f32)
#define LDG2 40          // big-GEMM chunk lead dim

// ---------------- device scratch ----------------
__device__ float d_m[BB];
__device__ float d_h1[2][2][BB*HH];
__device__ float d_h2[2][2][BB*HH];
__device__ float d_p2[TT][BB][H2];
__device__ __nv_bfloat16 d_W1hi[2][1024*256];
__device__ __nv_bfloat16 d_W1lo[2][1024*256];
__device__ __nv_bfloat16 d_Whh2hi[2][1024*256];
__device__ __nv_bfloat16 d_Whh2lo[2][1024*256];
__device__ __nv_bfloat16 d_Wih2hi[2048*512];
__device__ __nv_bfloat16 d_Wih2lo[2048*512];
__device__ float d_bx1[2][1024];
__device__ float d_bx2[2][1024];
__device__ float d_wix[2][1024*2];
__device__ __nv_bfloat16 d_A2hi[(size_t)TT*BB*512];   // masked p1, bf16 hi
__device__ __nv_bfloat16 d_A2lo[(size_t)TT*BB*512];   // masked p1, bf16 lo
__device__ float d_Z2[(size_t)TT*BB*2048];            // layer-2 input projection
__device__ int d_bar[2][16];

__device__ __forceinline__ float sigf(float x){ return 1.0f/(1.0f+__expf(-x)); }

// ---------------- mean ----------------
__global__ void mean_kernel(const float* __restrict__ x0){
    int b = blockIdx.x*blockDim.x + threadIdx.x;
    if (b < BB){
        float s = 0.f;
        #pragma unroll 4
        for (int t=0; t<TT; t++) s += x0[b*TT+t];
        d_m[b] = s*(1.0f/TT);
    }
}

// ---------------- zero states + barriers ----------------
__global__ void zero_kernel(){
    int i = blockIdx.x*blockDim.x + threadIdx.x;
    if (i < BB*HH){
        d_h1[0][0][i]=0.f; d_h1[0][1][i]=0.f;
        d_h2[0][0][i]=0.f; d_h2[0][1][i]=0.f;
    }
    if (i < 16){ d_bar[0][i]=0; d_bar[1][i]=0; }
}

// ---------------- weight prep: split + permute (r' = 4h+g) ----------------
__global__ void prep_weights(
    const float* __restrict__ Whh1f, const float* __restrict__ Whh1b,
    const float* __restrict__ Wih2f, const float* __restrict__ Whh2f,
    const float* __restrict__ Wih2b, const float* __restrict__ Whh2b,
    const float* __restrict__ Wih1f, const float* __restrict__ Wih1b,
    const float* __restrict__ bih1f, const float* __restrict__ bhh1f,
    const float* __restrict__ bih1b, const float* __restrict__ bhh1b,
    const float* __restrict__ bih2f, const float* __restrict__ bhh2f,
    const float* __restrict__ bih2b, const float* __restrict__ bhh2b)
{
    int stride = gridDim.x*blockDim.x;
    int idx = blockIdx.x*blockDim.x + threadIdx.x;
    // layer1 recurrent: [dir][r'=4h+g][256]
    for (int i = idx; i < 2*1024*256; i += stride){
        int dir = i/(1024*256); int r = (i/256)%1024; int k = i%256;
        int h = r>>2, g = r&3;
        const float* W = dir ? Whh1b : Whh1f;
        float w = W[(g*256+h)*256 + k];
        __nv_bfloat16 hi = __float2bfloat16(w);
        __nv_bfloat16 lo = __float2bfloat16(w - __bfloat162float(hi));
        d_W1hi[dir][r*256+k] = hi;
        d_W1lo[dir][r*256+k] = lo;
    }
    // layer2 recurrent: [dir][r'][256]
    for (int i = idx; i < 2*1024*256; i += stride){
        int dir = i/(1024*256); int r = (i/256)%1024; int k = i%256;
        int h = r>>2, g = r&3;
        const float* W = dir ? Whh2b : Whh2f;
        float w = W[(g*256+h)*256 + k];
        __nv_bfloat16 hi = __float2bfloat16(w);
        __nv_bfloat16 lo = __float2bfloat16(w - __bfloat162float(hi));
        d_Whh2hi[dir][r*256+k] = hi;
        d_Whh2lo[dir][r*256+k] = lo;
    }
    // layer2 input: [n = dir*1024 + r'][512]
    for (int i = idx; i < 2048*512; i += stride){
        int n = i>>9, k = i&511;
        int dir = n>>10, r = n&1023;
        int h = r>>2, g = r&3;
        const float* W = dir ? Wih2b : Wih2f;
        float w = W[(g*256+h)*512 + k];
        __nv_bfloat16 hi = __float2bfloat16(w);
        __nv_bfloat16 lo = __float2bfloat16(w - __bfloat162float(hi));
        d_Wih2hi[i] = hi;
        d_Wih2lo[i] = lo;
    }
    // biases + layer1 input weights (permuted)
    for (int i = idx; i < 2*1024; i += stride){
        int dir = i>>10; int r = i&1023;
        int h = r>>2, g = r&3;
        const float* b1i = dir ? bih1b : bih1f; const float* b1h = dir ? bhh1b : bhh1f;
        const float* b2i = dir ? bih2b : bih2f; const float* b2h = dir ? bhh2b : bhh2f;
        d_bx1[dir][r] = b1i[g*256+h] + b1h[g*256+h];
        d_bx2[dir][r] = b2i[g*256+h] + b2h[g*256+h];
        const float* Wi = dir ? Wih1b : Wih1f;
        d_wix[dir][r*2+0] = Wi[(g*256+h)*2 + 0];
        d_wix[dir][r*2+1] = Wi[(g*256+h)*2 + 1];
    }
}

// ---------------- persistent recurrent LSTM ----------------
// grid (8 ntile, 8 btile, 2 dir) = 128 CTAs, 1/SM (smem-forced). 256 threads.
// W (hi/lo) resident in smem for all 100 steps; A chunks double-buffered;
// c state in registers; per-(btile,dir) group barrier between steps.
#define PERSIST_SMEM (2048 + 2*128*LDW*2 + 2*2*128*LDA*2)   // 210944

template<int LAYER>
__global__ void __launch_bounds__(256,1) lstm_persist(
    const float* __restrict__ x0,
    const float* __restrict__ mrec,     // mask1 (L1) / mask3 (L2)
    const float* __restrict__ mask2)    // L1 only (for A2 write)
{
    extern __shared__ char sm[];
    float* sBias = (float*)sm;                         // 512 B
    float* sWix  = (float*)(sm + 512);                 // 1 KB
    __nv_bfloat16* sWh = (__nv_bfloat16*)(sm + 2048);
    __nv_bfloat16* sWl = sWh + 128*LDW;
    __nv_bfloat16* sAbase = (__nv_bfloat16*)(sm + 2048 + 2*128*LDW*2);
    float* sC = (float*)sAbase;

    const int tid = threadIdx.x, wid = tid>>5;
    const int ntile = blockIdx.x, btile = blockIdx.y, dir = blockIdx.z;
    const int gr0 = ntile*128;
    int* ctr = &d_bar[LAYER-1][dir*8 + btile];

    const __nv_bfloat16 *Whi, *Wlo; const float* bx;
    float *hp0, *hp1;
    if (LAYER==1){
        Whi=d_W1hi[dir]; Wlo=d_W1lo[dir]; bx=d_bx1[dir];
        hp0=d_h1[0][dir]; hp1=d_h1[1][dir];
    } else {
        Whi=d_Whh2hi[dir]; Wlo=d_Whh2lo[dir]; bx=d_bx2[dir];
        hp0=d_h2[0][dir]; hp1=d_h2[1][dir];
    }

    // stage resident W (hi/lo), biases, input weights
    #pragma unroll
    for (int it=0; it<16; it++){
        int lin = tid + it*256;
        int r = lin>>5, seg = lin&31;
        *(uint4*)(sWh + r*LDW + seg*8) = *(const uint4*)(Whi + (gr0+r)*256 + seg*8);
        *(uint4*)(sWl + r*LDW + seg*8) = *(const uint4*)(Wlo + (gr0+r)*256 + seg*8);
    }
    if (tid < 128) sBias[tid] = bx[gr0 + tid];
    if (LAYER==1) sWix[tid] = d_wix[dir][gr0*2 + tid];
    __syncthreads();

    const int wm = (wid&3)*32, wn = (wid>>2)*64;
    const int row = tid>>1, half = tid&1;
    const int bE = btile*128 + row;

    float creg[16];
    #pragma unroll
    for (int i=0;i<16;i++) creg[i]=0.f;

    for (int t=0; t<TT; t++){
        const int tin = dir ? (TT-1-t) : t;
        const float* h_in = (t&1) ? hp1 : hp0;
        float* h_out = (t&1) ? hp0 : hp1;

        wmma::fragment<wmma::accumulator,16,16,16,float> acc[2][4];
        #pragma unroll
        for (int i=0;i<2;i++)
            #pragma unroll
            for (int j=0;j<4;j++) wmma::fill_fragment(acc[i][j], 0.f);

        if (t > 0){
            // stage chunk 0
            {
                __nv_bfloat16* ah = sAbase;
                __nv_bfloat16* al = sAbase + 128*LDA;
                #pragma unroll
                for (int it=0; it<16; it++){
                    int lin = tid + it*256; int r = lin>>5, pr = lin&31;
                    int gi = (btile*128 + r)*HH + pr*2;
                    float2 hv = *(const float2*)&h_in[gi];
                    float2 mv = *(const float2*)&mrec[gi];
                    float v0 = hv.x*mv.x, v1 = hv.y*mv.y;
                    __nv_bfloat16 b0 = __float2bfloat16(v0), b1 = __float2bfloat16(v1);
                    __nv_bfloat16 l0 = __float2bfloat16(v0 - __bfloat162float(b0));
                    __nv_bfloat16 l1 = __float2bfloat16(v1 - __bfloat162float(b1));
                    *(__nv_bfloat162*)(ah + r*LDA + pr*2) = __halves2bfloat162(b0,b1);
                    *(__nv_bfloat162*)(al + r*LDA + pr*2) = __halves2bfloat162(l0,l1);
                }
            }
            __syncthreads();
            #pragma unroll
            for (int kc=0; kc<4; kc++){
                float2 v[16];
                if (kc < 3){       // prefetch next chunk into registers first
                    #pragma unroll
                    for (int it=0; it<16; it++){
                        int lin = tid + it*256; int r = lin>>5, pr = lin&31;
                        int gi = (btile*128 + r)*HH + (kc+1)*64 + pr*2;
                        float2 hv = *(const float2*)&h_in[gi];
                        float2 mv = *(const float2*)&mrec[gi];
                        v[it].x = hv.x*mv.x; v[it].y = hv.y*mv.y;
                    }
                }
                // MMA on current buffer
                {
                    const __nv_bfloat16* ah = sAbase + (kc&1)*2*128*LDA;
                    const __nv_bfloat16* al = ah + 128*LDA;
                    #pragma unroll
                    for (int k16=0; k16<4; k16++){
                        wmma::fragment<wmma::matrix_a,16,16,16,__nv_bfloat16,wmma::row_major> fa[2], fal[2];
                        wmma::fragment<wmma::matrix_b,16,16,16,__nv_bfloat16,wmma::col_major> fb[4], fbl[4];
                        #pragma unroll
                        for (int i=0;i<2;i++){
                            wmma::load_matrix_sync(fa[i],  ah + (wm+16*i)*LDA + k16*16, LDA);
                            wmma::load_matrix_sync(fal[i], al + (wm+16*i)*LDA + k16*16, LDA);
                        }
                        #pragma unroll
                        for (int j=0;j<4;j++){
                            wmma::load_matrix_sync(fb[j],  sWh + (wn+16*j)*LDW + kc*64 + k16*16, LDW);
                            wmma::load_matrix_sync(fbl[j], sWl + (wn+16*j)*LDW + kc*64 + k16*16, LDW);
                        }
                        #pragma unroll
                        for (int i=0;i<2;i++)
                            #pragma unroll
                            for (int j=0;j<4;j++){
                                wmma::mma_sync(acc[i][j], fa[i],  fb[j],  acc[i][j]);
                                wmma::mma_sync(acc[i][j], fal[i], fb[j],  acc[i][j]);
                                wmma::mma_sync(acc[i][j], fa[i],  fbl[j], acc[i][j]);
                            }
                    }
                }
                if (kc < 3){       // split + store prefetched chunk
                    __nv_bfloat16* ah = sAbase + ((kc+1)&1)*2*128*LDA;
                    __nv_bfloat16* al = ah + 128*LDA;
                    #pragma unroll
                    for (int it=0; it<16; it++){
                        int lin = tid + it*256; int r = lin>>5, pr = lin&31;
                        float v0 = v[it].x, v1 = v[it].y;
                        __nv_bfloat16 b0 = __float2bfloat16(v0), b1 = __float2bfloat16(v1);
                        __nv_bfloat16 l0 = __float2bfloat16(v0 - __bfloat162float(b0));
                        __nv_bfloat16 l1 = __float2bfloat16(v1 - __bfloat162float(b1));
                        *(__nv_bfloat162*)(ah + r*LDA + pr*2) = __halves2bfloat162(b0,b1);
                        *(__nv_bfloat162*)(al + r*LDA + pr*2) = __halves2bfloat162(l0,l1);
                    }
                }
                __syncthreads();
            }
        }

        // ---- epilogue ----
        #pragma unroll
        for (int i=0;i<2;i++)
            #pragma unroll
            for (int j=0;j<4;j++)
                wmma::store_matrix_sync(sC + (wm+16*i)*LDC + wn + 16*j, acc[i][j],
                                        LDC, wmma::mem_row_major);
        __syncthreads();

        float xv = 0.f, mb = 0.f;
        if (LAYER==1){ mb = d_m[bE]; xv = x0[bE*TT + tin] - mb; }
        float4 z[16];
        if (LAYER==2){
            const float* zp = d_Z2 + ((size_t)tin*BB + bE)*2048 + dir*1024 + gr0 + half*64;
            #pragma unroll
            for (int j=0;j<16;j++) z[j] = *(const float4*)(zp + j*4);
        }
        const float* cr = sC + row*LDC + half*64;
        #pragma unroll
        for (int hh=0; hh<16; hh++){
            int rl = half*64 + hh*4;
            float g0 = cr[hh*4+0] + sBias[rl+0];
            float g1 = cr[hh*4+1] + sBias[rl+1];
            float g2 = cr[hh*4+2] + sBias[rl+2];
            float g3 = cr[hh*4+3] + sBias[rl+3];
            if (LAYER==1){
                g0 += sWix[(rl+0)*2]*xv + sWix[(rl+0)*2+1]*mb;
                g1 += sWix[(rl+1)*2]*xv + sWix[(rl+1)*2+1]*mb;
                g2 += sWix[(rl+2)*2]*xv + sWix[(rl+2)*2+1]*mb;
                g3 += sWix[(rl+3)*2]*xv + sWix[(rl+3)*2+1]*mb;
            } else {
                g0 += z[hh].x; g1 += z[hh].y; g2 += z[hh].z; g3 += z[hh].w;
            }
            float ig = sigf(g0), fg = sigf(g1), gt = tanhf(g2), og = sigf(g3);
            float cn = fg*creg[hh] + ig*gt;
            float hn = og*tanhf(cn);
            creg[hh] = cn;
            int hglob = ntile*32 + half*16 + hh;
            h_out[bE*HH + hglob] = hn;
            if (LAYER==1){
                float a = hn * mask2[bE*H2 + dir*HH + hglob];
                __nv_bfloat16 ah_ = __float2bfloat16(a);
                __nv_bfloat16 al_ = __float2bfloat16(a - __bfloat162float(ah_));
                size_t ai = ((size_t)t*BB + bE)*512 + dir*HH + hglob;
                d_A2hi[ai] = ah_; d_A2lo[ai] = al_;
            } else {
                d_p2[t][bE][dir*HH + hglob] = hn;
            }
        }

        // ---- group barrier (8 CTAs sharing (btile,dir)) ----
        if (t < TT-1){
            __threadfence();
            __syncthreads();
            if (tid == 0){
                atomicAdd(ctr, 1);
                int target = 8*(t+1);
                while (atomicAdd(ctr, 0) < target) __nanosleep(40);
                __threadfence();
            }
            __syncthreads();
        }
    }
}

// ---------------- big GEMM: Z2 = A2 @ Wih2^T ----------------
// M=102400 (t*1024+b), N=2048 (dir*1024+r'), K=512. grid (16 ntile, 800 mblock).
#define GEMM_SMEM (8*128*LDG2*2)    // 81920

__global__ void __launch_bounds__(256,1) gemm_z2(){
    extern __shared__ char sm[];
    __nv_bfloat16* buf = (__nv_bfloat16*)sm;
    float* sC = (float*)sm;
    const int tid = threadIdx.x, wid = tid>>5;
    const int n0 = blockIdx.x*128;
    const int m0 = blockIdx.y*128;
    const int wm = (wid&3)*32, wn = (wid>>2)*64;
    const int SETSZ = 4*128*LDG2;

    wmma::fragment<wmma::accumulator,16,16,16,float> acc[2][4];
    #pragma unroll
    for (int i=0;i<2;i++)
        #pragma unroll
        for (int j=0;j<4;j++) wmma::fill_fragment(acc[i][j], 0.f);

    // stage chunk 0
    {
        __nv_bfloat16* p = buf;
        #pragma unroll
        for (int it=0; it<2; it++){
            int lin = tid + it*256; int r = lin>>2, seg = lin&3;
            size_t sa = (size_t)(m0+r)*512 + seg*8;
            size_t sw = (size_t)(n0+r)*512 + seg*8;
            *(uint4*)(p + r*LDG2 + seg*8)              = *(const uint4*)(d_A2hi + sa);
            *(uint4*)(p + 128*LDG2 + r*LDG2 + seg*8)   = *(const uint4*)(d_A2lo + sa);
            *(uint4*)(p + 2*128*LDG2 + r*LDG2 + seg*8) = *(const uint4*)(d_Wih2hi + sw);
            *(uint4*)(p + 3*128*LDG2 + r*LDG2 + seg*8) = *(const uint4*)(d_Wih2lo + sw);
        }
    }
    __syncthreads();

    for (int kc=0; kc<16; kc++){
        uint4 v[8];
        if (kc < 15){
            #pragma unroll
            for (int it=0; it<2; it++){
                int lin = tid + it*256; int r = lin>>2, seg = lin&3;
                size_t sa = (size_t)(m0+r)*512 + (kc+1)*32 + seg*8;
                size_t sw = (size_t)(n0+r)*512 + (kc+1)*32 + seg*8;
                v[it*4+0] = *(const uint4*)(d_A2hi + sa);
                v[it*4+1] = *(const uint4*)(d_A2lo + sa);
                v[it*4+2] = *(const uint4*)(d_Wih2hi + sw);
                v[it*4+3] = *(const uint4*)(d_Wih2lo + sw);
            }
        }
        {
            const __nv_bfloat16* p = buf + (kc&1)*SETSZ;
            const __nv_bfloat16* ah = p;
            const __nv_bfloat16* al = p + 128*LDG2;
            const __nv_bfloat16* wh = p + 2*128*LDG2;
            const __nv_bfloat16* wl = p + 3*128*LDG2;
            #pragma unroll
            for (int k16=0; k16<2; k16++){
                wmma::fragment<wmma::matrix_a,16,16,16,__nv_bfloat16,wmma::row_major> fa[2], fal[2];
                wmma::fragment<wmma::matrix_b,16,16,16,__nv_bfloat16,wmma::col_major> fb[4], fbl[4];
                #pragma unroll
                for (int i=0;i<2;i++){
                    wmma::load_matrix_sync(fa[i],  ah + (wm+16*i)*LDG2 + k16*16, LDG2);
                    wmma::load_matrix_sync(fal[i], al + (wm+16*i)*LDG2 + k16*16, LDG2);
                }
                #pragma unroll
                for (int j=0;j<4;j++){
                    wmma::load_matrix_sync(fb[j],  wh + (wn+16*j)*LDG2 + k16*16, LDG2);
                    wmma::load_matrix_sync(fbl[j], wl + (wn+16*j)*LDG2 + k16*16, LDG2);
                }
                #pragma unroll
                for (int i=0;i<2;i++)
                    #pragma unroll
                    for (int j=0;j<4;j++){
                        wmma::mma_sync(acc[i][j], fa[i],  fb[j],  acc[i][j]);
                        wmma::mma_sync(acc[i][j], fal[i], fb[j],  acc[i][j]);
                        wmma::mma_sync(acc[i][j], fa[i],  fbl[j], acc[i][j]);
                    }
            }
        }
        if (kc < 15){
            __nv_bfloat16* p = buf + ((kc+1)&1)*SETSZ;
            #pragma unroll
            for (int it=0; it<2; it++){
                int lin = tid + it*256; int r = lin>>2, seg = lin&3;
                *(uint4*)(p + r*LDG2 + seg*8)              = v[it*4+0];
                *(uint4*)(p + 128*LDG2 + r*LDG2 + seg*8)   = v[it*4+1];
                *(uint4*)(p + 2*128*LDG2 + r*LDG2 + seg*8) = v[it*4+2];
                *(uint4*)(p + 3*128*LDG2 + r*LDG2 + seg*8) = v[it*4+3];
            }
        }
        __syncthreads();
    }

    // epilogue: fp32 Z2 out
    #pragma unroll
    for (int i=0;i<2;i++)
        #pragma unroll
        for (int j=0;j<4;j++)
            wmma::store_matrix_sync(sC + (wm+16*i)*LDC + wn + 16*j, acc[i][j],
                                    LDC, wmma::mem_row_major);
    __syncthreads();
    const int row = tid>>1, half = tid&1;
    float* zp = d_Z2 + (size_t)(m0+row)*2048 + n0 + half*64;
    const float* cr = sC + row*LDC + half*64;
    #pragma unroll
    for (int j=0;j<16;j++)
        *(float4*)(zp + j*4) = *(const float4*)(cr + j*4);
}

// ---------------- output projection ----------------
__global__ void proj_kernel(const float* __restrict__ Wout,
                            const float* __restrict__ bout,
                            const float* __restrict__ mask4,
                            float* __restrict__ out)
{
    int w = blockIdx.x*(blockDim.x>>5) + (threadIdx.x>>5);
    int lane = threadIdx.x & 31;
    if (w >= BB*TT) return;
    int b = w/TT, t = w%TT;
    float s = 0.f;
    #pragma unroll
    for (int j = lane; j < H2; j += 32)
        s += d_p2[t][b][j] * mask4[b*H2 + j] * Wout[j];
    #pragma unroll
    for (int o = 16; o > 0; o >>= 1) s += __shfl_xor_sync(0xffffffffu, s, o);
    if (lane == 0) out[b*TT + t] = s + bout[0] + d_m[b];
}

// ---------------- launcher ----------------
extern "C" void kernel_launch(void* const* d_in, const int* in_sizes, int n_in,
                              void* d_out, int out_size)
{
    const float* x0    = (const float*)d_in[0];
    const float* Wih1f = (const float*)d_in[1];
    const float* Whh1f = (const float*)d_in[2];
    const float* bih1f = (const float*)d_in[3];
    const float* bhh1f = (const float*)d_in[4];
    const float* Wih1b = (const float*)d_in[5];
    const float* Whh1b = (const float*)d_in[6];
    const float* bih1b = (const float*)d_in[7];
    const float* bhh1b = (const float*)d_in[8];
    const float* Wih2f = (const float*)d_in[9];
    const float* Whh2f = (const float*)d_in[10];
    const float* bih2f = (const float*)d_in[11];
    const float* bhh2f = (const float*)d_in[12];
    const float* Wih2b = (const float*)d_in[13];
    const float* Whh2b = (const float*)d_in[14];
    const float* bih2b = (const float*)d_in[15];
    const float* bhh2b = (const float*)d_in[16];
    const float* Wout  = (const float*)d_in[17];
    const float* bout  = (const float*)d_in[18];
    const float* mask1 = (const float*)d_in[19];
    const float* mask2 = (const float*)d_in[20];
    const float* mask3 = (const float*)d_in[21];
    const float* mask4 = (const float*)d_in[22];
    float* out = (float*)d_out;

    cudaFuncSetAttribute(lstm_persist<1>, cudaFuncAttributeMaxDynamicSharedMemorySize, PERSIST_SMEM);
    cudaFuncSetAttribute(lstm_persist<2>, cudaFuncAttributeMaxDynamicSharedMemorySize, PERSIST_SMEM);
    cudaFuncSetAttribute(gemm_z2, cudaFuncAttributeMaxDynamicSharedMemorySize, GEMM_SMEM);

    mean_kernel<<<(BB+255)/256, 256>>>(x0);
    zero_kernel<<<(BB*HH+255)/256, 256>>>();
    prep_weights<<<1024, 256>>>(Whh1f, Whh1b, Wih2f, Whh2f, Wih2b, Whh2b,
                                Wih1f, Wih1b,
                                bih1f, bhh1f, bih1b, bhh1b,
                                bih2f, bhh2f, bih2b, bhh2b);

    lstm_persist<1><<<dim3(8,8,2), 256, PERSIST_SMEM>>>(x0, mask1, mask2);
    gemm_z2<<<dim3(16,800), 256, GEMM_SMEM>>>();
    lstm_persist<2><<<dim3(8,8,2), 256, PERSIST_SMEM>>>(nullptr, mask3, nullptr);

    proj_kernel<<<(BB*TT+7)/8, 256>>>(Wout, bout, mask4, out);
}